// round 8
// baseline (speedup 1.0000x reference)
#include <cuda_runtime.h>
#include <cstdint>

// SeparableConv3D: x[8,3,32,256,256] fp32, depthwise K=5 cross-correlation
// along W, then H, then T, zero 'same' padding each stage.
//
// Fused, software-pipelined, shuffle-free, t-major staging:
//   phase A: 1-row-ahead LDG register prefetch (item A: all threads,
//            item B: threads 128-191), committed via 2x STS.64 into a
//            SHIFTED slab (offset 4q+2) so phase B needs only 2 LDS.128
//   phase B (lane=t, wg=w-quad): W-conv (2 aligned LDS.128) + H-conv
//            register ring, transposed store s(t,w) -> sbufT[w][t]
//   phase C (warps 0-1; lane=w, tg=t-half): T-conv = 6 LDS.128 along t
//            per 16 outputs, from the PREVIOUS iteration's staging buffer
//   ONE __syncthreads per h-row; main loop unrolled 4x.

#define NN 8
#define CC 3
#define TT 32
#define HH 256
#define WW 256
#define KK 5

#define WT 32           // w outputs per block
#define HC 32           // h rows per block -> grid = 24*8*8 = 1536
#define XSTRIDE 44      // x slab row stride (floats); data lives at [2..41]
#define STR_T 36        // sbufT per-w stride along t

__global__ void __launch_bounds__(256, 4)
sepconv3d_fused(const float* __restrict__ x,
                const float* __restrict__ w1,   // along W
                const float* __restrict__ w2,   // along H
                const float* __restrict__ w3,   // along T
                float* __restrict__ out)
{
    __shared__ float xbuf[2][TT * XSTRIDE];
    __shared__ float sbufT[2][WT * STR_T];   // [w][t], s = after W+H conv

    const int tid  = threadIdx.x;
    const int lane = tid & 31;     // phase B: = t ; phase C: = w
    const int wg   = tid >> 5;     // phase B: w-quad

    const int bid = blockIdx.x;               // 0..1535
    const int nc  = bid >> 6;                  // n*3+c
    const int rem = bid & 63;
    const int wt  = rem >> 3;                   // 0..7
    const int hcb = rem & 7;                    // 0..7
    const int c   = nc % CC;

    const int w0 = wt * WT;
    const int h0 = hcb * HC;
    const size_t HW = (size_t)HH * WW;

    const float wW0 = w1[c*KK+0], wW1 = w1[c*KK+1], wW2 = w1[c*KK+2], wW3 = w1[c*KK+3], wW4 = w1[c*KK+4];
    const float wH0 = w2[c*KK+0], wH1 = w2[c*KK+1], wH2 = w2[c*KK+2], wH3 = w2[c*KK+3], wH4 = w2[c*KK+4];
    const float wT0 = w3[c*KK+0], wT1 = w3[c*KK+1], wT2 = w3[c*KK+2], wT3 = w3[c*KK+3], wT4 = w3[c*KK+4];

    const float* xb = x   + (size_t)nc * (TT * HW);
    float*       ob = out + (size_t)nc * (TT * HW);

    // ---- slab-load geometry: item A = tid (all), item B = threads 128-191 ----
    const int trA = tid / 10,  qA = tid - trA * 10;
    const bool hasB = (tid >= 128) && (tid < 192);
    const int iB  = 256 + (tid - 128);
    const int trB = iB / 10,   qB = iB - trB * 10;
    const int gwA = w0 - 4 + 4 * qA;
    const int gwB = w0 - 4 + 4 * qB;
    const bool wvA = (gwA >= 0) && (gwA < WW);
    const bool wvB = hasB && (gwB >= 0) && (gwB < WW);
    // incremental prefetch pointers (start at h_in = h0 - 1, it=0's prefetch)
    const float* ptrA = xb + (size_t)trA * HW + (wvA ? gwA : 0) + (size_t)(h0 - 1) * WW;
    const float* ptrB = xb + (size_t)trB * HW + (wvB ? gwB : 0) + (size_t)(h0 - 1) * WW;

    // smem commit addresses: SHIFTED by +2 floats (slab[i] = x[w0-6+i])
    float* const xsA0 = &xbuf[0][trA * XSTRIDE + 4 * qA + 2];
    float* const xsA1 = &xbuf[1][trA * XSTRIDE + 4 * qA + 2];
    float* const xsB0 = &xbuf[0][trB * XSTRIDE + 4 * qB + 2];
    float* const xsB1 = &xbuf[1][trB * XSTRIDE + 4 * qB + 2];

    // ---- phase C geometry: warps 0-1; lane = w, tg = t-half (16 outputs) ----
    const bool doC  = (tid < 64);
    const int tg    = tid >> 5;                  // 0..1 (valid when doC)
    const int t0    = 16 * tg;
    const int cbase = lane * STR_T;
    const int q0off = cbase + max(t0 - 4, 0);    // quad t0-4..t0-1 (clamped)
    const int q1off = cbase + t0;
    const int q5off = cbase + min(t0 + 16, 28);  // quad t0+16..t0+19 (clamped)
    const float mlo = (tg == 0) ? 0.f : 1.f;     // zero-pad t<0
    const float mhi = (tg == 1) ? 0.f : 1.f;     // zero-pad t>31
    // incremental output pointer: row ho = h0 + it - 5 used only when it>=5
    float* op = ob + (size_t)t0 * HW + w0 + lane + (size_t)h0 * WW - 5 * WW;

    // H-conv register ring
    float4 g0 = {0,0,0,0}, g1 = {0,0,0,0}, g2 = {0,0,0,0}, g3 = {0,0,0,0}, g4 = {0,0,0,0};
    const int scolbase = 4 * wg;
    float* const sbB0 = &sbufT[0][scolbase * STR_T + lane];   // phase-B store base
    float* const sbB1 = &sbufT[1][scolbase * STR_T + lane];

    // ---- prologue: load row it=0 (h_in = h0-2) into xbuf[0] ----
    {
        const int h_in = h0 - 2;
        const bool hv = (h_in >= 0);
        float4 v = {0,0,0,0};
        if (hv && wvA) v = *reinterpret_cast<const float4*>(ptrA - WW);
        *reinterpret_cast<float2*>(xsA0)     = make_float2(v.x, v.y);
        *reinterpret_cast<float2*>(xsA0 + 2) = make_float2(v.z, v.w);
        if (hasB) {
            float4 u = {0,0,0,0};
            if (hv && wvB) u = *reinterpret_cast<const float4*>(ptrB - WW);
            *reinterpret_cast<float2*>(xsB0)     = make_float2(u.x, u.y);
            *reinterpret_cast<float2*>(xsB0 + 2) = make_float2(u.z, u.w);
        }
    }
    __syncthreads();

    #pragma unroll 4
    for (int it = 0; it < HC + 4; ++it) {
        const int cur = it & 1;

        // ---- 1. prefetch next x row (h_in = h0 - 1 + it) ----
        float4 p0 = {0,0,0,0}, p1 = {0,0,0,0};
        {
            const int h_in = h0 - 1 + it;
            const bool hv = (it + 1 < HC + 4) && (h_in >= 0) && (h_in < HH);
            if (hv && wvA) p0 = *reinterpret_cast<const float4*>(ptrA);
            if (hv && wvB) p1 = *reinterpret_cast<const float4*>(ptrB);
            ptrA += WW; ptrB += WW;
        }

        // ---- 2. phase B: W-conv (2 aligned LDS.128) + H-ring -> sbufT[cur] ----
        {
            // slab[i] = x[w0-6+i]; window x[w-2..w+5] = slab[4wg+4 .. 4wg+11]
            const float* row = &xbuf[cur][lane * XSTRIDE + scolbase + 4];
            float4 m = *reinterpret_cast<const float4*>(row);       // x[w-2..w+1]
            float4 n = *reinterpret_cast<const float4*>(row + 4);   // x[w+2..w+5]

            float4 r;
            r.x = wW0*m.x + wW1*m.y + wW2*m.z + wW3*m.w + wW4*n.x;
            r.y = wW0*m.y + wW1*m.z + wW2*m.w + wW3*n.x + wW4*n.y;
            r.z = wW0*m.z + wW1*m.w + wW2*n.x + wW3*n.y + wW4*n.z;
            r.w = wW0*m.w + wW1*n.x + wW2*n.y + wW3*n.z + wW4*n.w;

            g0 = g1; g1 = g2; g2 = g3; g3 = g4; g4 = r;

            if (it >= 4) {
                float sx = wH0*g0.x + wH1*g1.x + wH2*g2.x + wH3*g3.x + wH4*g4.x;
                float sy = wH0*g0.y + wH1*g1.y + wH2*g2.y + wH3*g3.y + wH4*g4.y;
                float sz = wH0*g0.z + wH1*g1.z + wH2*g2.z + wH3*g3.z + wH4*g4.z;
                float sw = wH0*g0.w + wH1*g1.w + wH2*g2.w + wH3*g3.w + wH4*g4.w;
                float* sc = cur ? sbB1 : sbB0;
                sc[0 * STR_T] = sx;
                sc[1 * STR_T] = sy;
                sc[2 * STR_T] = sz;
                sc[3 * STR_T] = sw;
            }
        }

        // ---- 3. phase C (warps 0-1): T-conv from PREVIOUS sbufT, 16 t-outputs ----
        if (doC && it >= 5) {
            const float* sb = sbufT[cur ^ 1];
            float4 q0 = *reinterpret_cast<const float4*>(sb + q0off);
            float4 q1 = *reinterpret_cast<const float4*>(sb + q1off);
            float4 q2 = *reinterpret_cast<const float4*>(sb + q1off + 4);
            float4 q3 = *reinterpret_cast<const float4*>(sb + q1off + 8);
            float4 q4 = *reinterpret_cast<const float4*>(sb + q1off + 12);
            float4 q5 = *reinterpret_cast<const float4*>(sb + q5off);
            q0.z *= mlo; q0.w *= mlo;     // zero-pad t<0
            q5.x *= mhi; q5.y *= mhi;     // zero-pad t>31

            float f[20] = {q0.z, q0.w,
                           q1.x, q1.y, q1.z, q1.w,
                           q2.x, q2.y, q2.z, q2.w,
                           q3.x, q3.y, q3.z, q3.w,
                           q4.x, q4.y, q4.z, q4.w,
                           q5.x, q5.y};
            #pragma unroll
            for (int k = 0; k < 16; ++k)
                op[(size_t)k * HW] =
                    wT0*f[k] + wT1*f[k+1] + wT2*f[k+2] + wT3*f[k+3] + wT4*f[k+4];
        }
        op += WW;

        // ---- 4. commit prefetched x row into xbuf[cur^1] (2x STS.64, shifted) ----
        {
            float* d = cur ? xsA0 : xsA1;
            *reinterpret_cast<float2*>(d)     = make_float2(p0.x, p0.y);
            *reinterpret_cast<float2*>(d + 2) = make_float2(p0.z, p0.w);
            if (hasB) {
                float* e = cur ? xsB0 : xsB1;
                *reinterpret_cast<float2*>(e)     = make_float2(p1.x, p1.y);
                *reinterpret_cast<float2*>(e + 2) = make_float2(p1.z, p1.w);
            }
        }

        __syncthreads();
        // barrier orders: xbuf[cur^1] STS vs next-iter LDS; sbufT[cur] writes vs
        // next-iter phase-C reads; phase-C reads of sbufT[cur^1] vs iter+1 writes.
    }

    // ---- epilogue: last output row from sbufT[(HC+3)&1], ho = h0+HC-1 ----
    if (doC) {
        const float* sb = sbufT[(HC + 3) & 1];
        float4 q0 = *reinterpret_cast<const float4*>(sb + q0off);
        float4 q1 = *reinterpret_cast<const float4*>(sb + q1off);
        float4 q2 = *reinterpret_cast<const float4*>(sb + q1off + 4);
        float4 q3 = *reinterpret_cast<const float4*>(sb + q1off + 8);
        float4 q4 = *reinterpret_cast<const float4*>(sb + q1off + 12);
        float4 q5 = *reinterpret_cast<const float4*>(sb + q5off);
        q0.z *= mlo; q0.w *= mlo;
        q5.x *= mhi; q5.y *= mhi;

        float f[20] = {q0.z, q0.w,
                       q1.x, q1.y, q1.z, q1.w,
                       q2.x, q2.y, q2.z, q2.w,
                       q3.x, q3.y, q3.z, q3.w,
                       q4.x, q4.y, q4.z, q4.w,
                       q5.x, q5.y};
        // op has been advanced HC+4 times: points at row h0 + HC - 1
        #pragma unroll
        for (int k = 0; k < 16; ++k)
            op[(size_t)k * HW] =
                wT0*f[k] + wT1*f[k+1] + wT2*f[k+2] + wT3*f[k+3] + wT4*f[k+4];
    }
}

extern "C" void kernel_launch(void* const* d_in, const int* in_sizes, int n_in,
                              void* d_out, int out_size)
{
    const float* x  = (const float*)d_in[0];
    const float* w1 = (const float*)d_in[1];
    const float* w2 = (const float*)d_in[2];
    const float* w3 = (const float*)d_in[3];
    float* out = (float*)d_out;

    // 24 (n*c) * 8 (w tiles) * 8 (h chunks) = 1536 blocks
    sepconv3d_fused<<<NN * CC * (WW / WT) * (HH / HC), 256>>>(x, w1, w2, w3, out);
}

// round 9
// speedup vs baseline: 1.4805x; 1.4805x over previous
#include <cuda_runtime.h>
#include <cstdint>

// SeparableConv3D: x[8,3,32,256,256] fp32, depthwise K=5 cross-correlation
// along W, then H, then T, zero 'same' padding each stage.
//
// Fused, 2-rows-per-iteration software pipeline (LDG prefetch, no cp.async):
//   phase A: prefetch 2 x-rows into registers (item A: all threads,
//            item B: threads 0-63), commit via aligned STS.128 at iter end
//   phase B (lane=t, wg=w-quad): W-conv both rows + H-conv ring (shift by 2),
//            transposed store s(t,w) -> sbufT[cur][row][w][t]
//   phase C (all warps; warps 0-3 row a, warps 4-7 row b; lane=w, tg=t-octet):
//            T-conv = 4 LDS.128 along t per 8 outputs, from PREVIOUS sbufT
//   ONE __syncthreads per 2 h-rows.

#define NN 8
#define CC 3
#define TT 32
#define HH 256
#define WW 256
#define KK 5

#define WT 32                 // w outputs per block
#define HC 32                 // h rows per block -> grid = 24*8*8 = 1536
#define NIT ((HC + 4) / 2)    // 18 iterations of 2 rows
#define XSTRIDE 44            // x slab row stride (conflict-free)
#define STR_T 36              // sbufT per-w stride along t

__global__ void __launch_bounds__(256, 4)
sepconv3d_fused(const float* __restrict__ x,
                const float* __restrict__ w1,   // along W
                const float* __restrict__ w2,   // along H
                const float* __restrict__ w3,   // along T
                float* __restrict__ out)
{
    __shared__ float xbuf[2][2][TT * XSTRIDE];     // [buf][row]
    __shared__ float sbufT[2][2][WT * STR_T];      // [buf][row][w][t]

    const int tid  = threadIdx.x;
    const int lane = tid & 31;     // phase B: = t ; phase C: = w
    const int wg   = tid >> 5;     // phase B: w-quad

    const int bid = blockIdx.x;               // 0..1535
    const int nc  = bid >> 6;                  // n*3+c
    const int rem = bid & 63;
    const int wt  = rem >> 3;                   // 0..7
    const int hcb = rem & 7;                    // 0..7
    const int c   = nc % CC;

    const int w0 = wt * WT;
    const int h0 = hcb * HC;
    const size_t HW = (size_t)HH * WW;

    const float wW0 = w1[c*KK+0], wW1 = w1[c*KK+1], wW2 = w1[c*KK+2], wW3 = w1[c*KK+3], wW4 = w1[c*KK+4];
    const float wH0 = w2[c*KK+0], wH1 = w2[c*KK+1], wH2 = w2[c*KK+2], wH3 = w2[c*KK+3], wH4 = w2[c*KK+4];
    const float wT0 = w3[c*KK+0], wT1 = w3[c*KK+1], wT2 = w3[c*KK+2], wT3 = w3[c*KK+3], wT4 = w3[c*KK+4];

    const float* xb = x   + (size_t)nc * (TT * HW);
    float*       ob = out + (size_t)nc * (TT * HW);

    // ---- slab-load geometry: item A = tid (all), item B = threads 0-63 ----
    const int trA = tid / 10,  qA = tid - trA * 10;
    const bool hasB = (tid < 64);
    const int iB  = 256 + tid;
    const int trB = iB / 10,   qB = iB - trB * 10;
    const int gwA = w0 - 4 + 4 * qA;
    const int gwB = w0 - 4 + 4 * qB;
    const bool wvA = (gwA >= 0) && (gwA < WW);
    const bool wvB = hasB && (gwB >= 0) && (gwB < WW);
    const float* gA = xb + (size_t)trA * HW + (wvA ? gwA : 0);   // + h*WW
    const float* gB = xb + (size_t)trB * HW + (wvB ? gwB : 0);

    // smem commit addresses (aligned STS.128)
    float* const xsA00 = &xbuf[0][0][trA * XSTRIDE + 4 * qA];
    float* const xsA01 = &xbuf[0][1][trA * XSTRIDE + 4 * qA];
    float* const xsA10 = &xbuf[1][0][trA * XSTRIDE + 4 * qA];
    float* const xsA11 = &xbuf[1][1][trA * XSTRIDE + 4 * qA];
    float* const xsB00 = &xbuf[0][0][trB * XSTRIDE + 4 * qB];
    float* const xsB01 = &xbuf[0][1][trB * XSTRIDE + 4 * qB];
    float* const xsB10 = &xbuf[1][0][trB * XSTRIDE + 4 * qB];
    float* const xsB11 = &xbuf[1][1][trB * XSTRIDE + 4 * qB];

    // ---- phase C geometry: lane = w; warps 0-3 row 0, warps 4-7 row 1 ----
    const int rr    = (tid >= 128) ? 1 : 0;      // which of the 2 rows
    const int tg    = wg & 3;                    // t-octet 0..3
    const int t0    = 8 * tg;
    const int cbase = lane * STR_T;
    const int q0off = cbase + max(t0 - 4, 0);    // quad t0-4..t0-1 (clamped)
    const int q1off = cbase + t0;                // quad t0..t0+3
    const int q2off = cbase + t0 + 4;            // quad t0+4..t0+7
    const int q3off = cbase + min(t0 + 8, 28);   // quad t0+8..t0+11 (clamped)
    const float mlo = (tg == 0) ? 0.f : 1.f;     // zero-pad t<0
    const float mhi = (tg == 3) ? 0.f : 1.f;     // zero-pad t>31
    // op advances 2 rows per iter; at iter ii it points at row h0 + 2ii - 6 + rr
    float* op = ob + (size_t)t0 * HW + w0 + lane
                   + (size_t)(h0 + rr) * WW - 6 * WW;

    // H-conv register ring: g1..g4 = W-conv of the last 4 input rows
    float4 g1 = {0,0,0,0}, g2 = {0,0,0,0}, g3 = {0,0,0,0}, g4 = {0,0,0,0};
    const int scolbase = 4 * wg;
    float* const sbB00 = &sbufT[0][0][scolbase * STR_T + lane];
    float* const sbB01 = &sbufT[0][1][scolbase * STR_T + lane];
    float* const sbB10 = &sbufT[1][0][scolbase * STR_T + lane];
    float* const sbB11 = &sbufT[1][1][scolbase * STR_T + lane];

    // ---- prologue: rows h0-2, h0-1 into xbuf[0][0..1] ----
    {
        float4 v0 = {0,0,0,0}, v1 = {0,0,0,0}, u0 = {0,0,0,0}, u1 = {0,0,0,0};
        if (wvA && h0 - 2 >= 0) v0 = *reinterpret_cast<const float4*>(gA + (size_t)(h0 - 2) * WW);
        if (wvA && h0 - 1 >= 0) v1 = *reinterpret_cast<const float4*>(gA + (size_t)(h0 - 1) * WW);
        *reinterpret_cast<float4*>(xsA00) = v0;
        *reinterpret_cast<float4*>(xsA01) = v1;
        if (hasB) {
            if (wvB && h0 - 2 >= 0) u0 = *reinterpret_cast<const float4*>(gB + (size_t)(h0 - 2) * WW);
            if (wvB && h0 - 1 >= 0) u1 = *reinterpret_cast<const float4*>(gB + (size_t)(h0 - 1) * WW);
            *reinterpret_cast<float4*>(xsB00) = u0;
            *reinterpret_cast<float4*>(xsB01) = u1;
        }
    }
    __syncthreads();

    #pragma unroll 2
    for (int ii = 0; ii < NIT; ++ii) {
        const int cur = ii & 1;

        // ---- 1. prefetch rows h0+2ii, h0+2ii+1 (for next iteration) ----
        float4 pa0 = {0,0,0,0}, pa1 = {0,0,0,0}, pb0 = {0,0,0,0}, pb1 = {0,0,0,0};
        {
            const bool iv = (ii + 1 < NIT);
            const int ha = h0 + 2 * ii;
            const int hb = ha + 1;
            if (iv && wvA && ha < HH) pa0 = *reinterpret_cast<const float4*>(gA + (size_t)ha * WW);
            if (iv && wvA && hb < HH) pa1 = *reinterpret_cast<const float4*>(gA + (size_t)hb * WW);
            if (iv && wvB && ha < HH) pb0 = *reinterpret_cast<const float4*>(gB + (size_t)ha * WW);
            if (iv && wvB && hb < HH) pb1 = *reinterpret_cast<const float4*>(gB + (size_t)hb * WW);
        }

        // ---- 2. phase B: W-conv both rows, H-conv, store s into sbufT[cur] ----
        float4 r_a, r_b;
        {
            const float* row0 = &xbuf[cur][0][lane * XSTRIDE + scolbase];
            float4 xa = *reinterpret_cast<const float4*>(row0);
            float4 xc = *reinterpret_cast<const float4*>(row0 + 4);
            float4 xe = *reinterpret_cast<const float4*>(row0 + 8);
            r_a.x = wW0*xa.z + wW1*xa.w + wW2*xc.x + wW3*xc.y + wW4*xc.z;
            r_a.y = wW0*xa.w + wW1*xc.x + wW2*xc.y + wW3*xc.z + wW4*xc.w;
            r_a.z = wW0*xc.x + wW1*xc.y + wW2*xc.z + wW3*xc.w + wW4*xe.x;
            r_a.w = wW0*xc.y + wW1*xc.z + wW2*xc.w + wW3*xe.x + wW4*xe.y;

            const float* row1 = &xbuf[cur][1][lane * XSTRIDE + scolbase];
            float4 xd = *reinterpret_cast<const float4*>(row1);
            float4 xf = *reinterpret_cast<const float4*>(row1 + 4);
            float4 xg = *reinterpret_cast<const float4*>(row1 + 8);
            r_b.x = wW0*xd.z + wW1*xd.w + wW2*xf.x + wW3*xf.y + wW4*xf.z;
            r_b.y = wW0*xd.w + wW1*xf.x + wW2*xf.y + wW3*xf.z + wW4*xf.w;
            r_b.z = wW0*xf.x + wW1*xf.y + wW2*xf.z + wW3*xf.w + wW4*xg.x;
            r_b.w = wW0*xf.y + wW1*xf.z + wW2*xf.w + wW3*xg.x + wW4*xg.y;
        }

        if (ii >= 2) {
            float* sa = cur ? sbB10 : sbB00;
            float* sb = cur ? sbB11 : sbB01;
            sa[0 * STR_T] = wH0*g1.x + wH1*g2.x + wH2*g3.x + wH3*g4.x + wH4*r_a.x;
            sa[1 * STR_T] = wH0*g1.y + wH1*g2.y + wH2*g3.y + wH3*g4.y + wH4*r_a.y;
            sa[2 * STR_T] = wH0*g1.z + wH1*g2.z + wH2*g3.z + wH3*g4.z + wH4*r_a.z;
            sa[3 * STR_T] = wH0*g1.w + wH1*g2.w + wH2*g3.w + wH3*g4.w + wH4*r_a.w;
            sb[0 * STR_T] = wH0*g2.x + wH1*g3.x + wH2*g4.x + wH3*r_a.x + wH4*r_b.x;
            sb[1 * STR_T] = wH0*g2.y + wH1*g3.y + wH2*g4.y + wH3*r_a.y + wH4*r_b.y;
            sb[2 * STR_T] = wH0*g2.z + wH1*g3.z + wH2*g4.z + wH3*r_a.z + wH4*r_b.z;
            sb[3 * STR_T] = wH0*g2.w + wH1*g3.w + wH2*g4.w + wH3*r_a.w + wH4*r_b.w;
        }
        // ring shift by 2 (rename)
        g1 = g3; g2 = g4; g3 = r_a; g4 = r_b;

        // ---- 3. phase C: T-conv from PREVIOUS sbufT; this thread's row = rr ----
        if (ii >= 3) {
            const float* sp = sbufT[cur ^ 1][rr];
            float4 q0 = *reinterpret_cast<const float4*>(sp + q0off);
            float4 q1 = *reinterpret_cast<const float4*>(sp + q1off);
            float4 q2 = *reinterpret_cast<const float4*>(sp + q2off);
            float4 q3 = *reinterpret_cast<const float4*>(sp + q3off);
            q0.z *= mlo; q0.w *= mlo;     // zero-pad t<0
            q3.x *= mhi; q3.y *= mhi;     // zero-pad t>31

            op[0]      = wT0*q0.z + wT1*q0.w + wT2*q1.x + wT3*q1.y + wT4*q1.z;
            op[1 * HW] = wT0*q0.w + wT1*q1.x + wT2*q1.y + wT3*q1.z + wT4*q1.w;
            op[2 * HW] = wT0*q1.x + wT1*q1.y + wT2*q1.z + wT3*q1.w + wT4*q2.x;
            op[3 * HW] = wT0*q1.y + wT1*q1.z + wT2*q1.w + wT3*q2.x + wT4*q2.y;
            op[4 * HW] = wT0*q1.z + wT1*q1.w + wT2*q2.x + wT3*q2.y + wT4*q2.z;
            op[5 * HW] = wT0*q1.w + wT1*q2.x + wT2*q2.y + wT3*q2.z + wT4*q2.w;
            op[6 * HW] = wT0*q2.x + wT1*q2.y + wT2*q2.z + wT3*q2.w + wT4*q3.x;
            op[7 * HW] = wT0*q2.y + wT1*q2.z + wT2*q2.w + wT3*q3.x + wT4*q3.y;
        }
        op += 2 * WW;

        // ---- 4. commit prefetched rows into xbuf[cur^1] ----
        *reinterpret_cast<float4*>(cur ? xsA00 : xsA10) = pa0;
        *reinterpret_cast<float4*>(cur ? xsA01 : xsA11) = pa1;
        if (hasB) {
            *reinterpret_cast<float4*>(cur ? xsB00 : xsB10) = pb0;
            *reinterpret_cast<float4*>(cur ? xsB01 : xsB11) = pb1;
        }

        __syncthreads();
        // barrier orders: xbuf[cur^1] STS vs next-iter LDS; sbufT[cur] writes vs
        // next-iter phase-C reads; phase-C reads of sbufT[cur^1] vs iter+1 writes.
    }

    // ---- epilogue: last 2 output rows from sbufT[(NIT-1)&1] ----
    {
        const float* sp = sbufT[(NIT - 1) & 1][rr];
        float4 q0 = *reinterpret_cast<const float4*>(sp + q0off);
        float4 q1 = *reinterpret_cast<const float4*>(sp + q1off);
        float4 q2 = *reinterpret_cast<const float4*>(sp + q2off);
        float4 q3 = *reinterpret_cast<const float4*>(sp + q3off);
        q0.z *= mlo; q0.w *= mlo;
        q3.x *= mhi; q3.y *= mhi;

        // op has advanced 2*NIT rows: points at row h0 + 30 + rr
        op[0]      = wT0*q0.z + wT1*q0.w + wT2*q1.x + wT3*q1.y + wT4*q1.z;
        op[1 * HW] = wT0*q0.w + wT1*q1.x + wT2*q1.y + wT3*q1.z + wT4*q1.w;
        op[2 * HW] = wT0*q1.x + wT1*q1.y + wT2*q1.z + wT3*q1.w + wT4*q2.x;
        op[3 * HW] = wT0*q1.y + wT1*q1.z + wT2*q1.w + wT3*q2.x + wT4*q2.y;
        op[4 * HW] = wT0*q1.z + wT1*q1.w + wT2*q2.x + wT3*q2.y + wT4*q2.z;
        op[5 * HW] = wT0*q1.w + wT1*q2.x + wT2*q2.y + wT3*q2.z + wT4*q2.w;
        op[6 * HW] = wT0*q2.x + wT1*q2.y + wT2*q2.z + wT3*q2.w + wT4*q3.x;
        op[7 * HW] = wT0*q2.y + wT1*q2.z + wT2*q2.w + wT3*q3.x + wT4*q3.y;
    }
}

extern "C" void kernel_launch(void* const* d_in, const int* in_sizes, int n_in,
                              void* d_out, int out_size)
{
    const float* x  = (const float*)d_in[0];
    const float* w1 = (const float*)d_in[1];
    const float* w2 = (const float*)d_in[2];
    const float* w3 = (const float*)d_in[3];
    float* out = (float*)d_out;

    // 24 (n*c) * 8 (w tiles) * 8 (h chunks) = 1536 blocks
    sepconv3d_fused<<<NN * CC * (WW / WT) * (HH / HC), 256>>>(x, w1, w2, w3, out);
}